// round 4
// baseline (speedup 1.0000x reference)
#include <cuda_runtime.h>
#include <cstdint>

#define BB   64
#define TT   512
#define DH   1024

// ---------------- device scratch (static, allocation-free) ----------------
__device__ float g_Gin_ih[1024 * 16];    // [j][d]
__device__ float g_Gin_hh[1024 * 16];    // [j][d]
__device__ float g_G56t_ih[256 * 16];    // [mp][e]  (transposed)
__device__ float g_G56t_hh[256 * 16];    // [mp][e]
__device__ float g_bias4[4096];          // [j][gate]
__device__ float g_ihg[(size_t)BB * TT * 4096]; // [b][t][j][gate]

typedef unsigned long long u64;

// ---------------- packed f32x2 helpers ------------------------------------
__device__ __forceinline__ u64 pk2(float lo, float hi) {
    u64 r; asm("mov.b64 %0, {%1,%2};" : "=l"(r) : "f"(lo), "f"(hi)); return r;
}
__device__ __forceinline__ void upk2(u64 v, float& lo, float& hi) {
    asm("mov.b64 {%0,%1}, %2;" : "=f"(lo), "=f"(hi) : "l"(v));
}
__device__ __forceinline__ u64 ffma2(u64 a, u64 b, u64 c) {
    u64 d; asm("fma.rn.f32x2 %0, %1, %2, %3;" : "=l"(d) : "l"(a), "l"(b), "l"(c));
    return d;
}
__device__ __forceinline__ u64 fadd2(u64 a, u64 b) {
    u64 d; asm("add.rn.f32x2 %0, %1, %2;" : "=l"(d) : "l"(a), "l"(b));
    return d;
}

// ---------------- fast activations (ex2/rcp approx, ~1e-6 accurate) -------
__device__ __forceinline__ float fexp2(float x) {
    float y; asm("ex2.approx.f32 %0, %1;" : "=f"(y) : "f"(x)); return y;
}
__device__ __forceinline__ float frcp(float x) {
    float y; asm("rcp.approx.f32 %0, %1;" : "=f"(y) : "f"(x)); return y;
}
__device__ __forceinline__ float sigmoidf(float x) {
    return frcp(1.0f + fexp2(-1.4426950408889634f * x));
}
__device__ __forceinline__ float tanhf_(float x) {
    return fmaf(2.0f, frcp(1.0f + fexp2(-2.8853900817779268f * x)), -1.0f);
}

// ---------------- cluster / DSMEM helpers ----------------------------------
__device__ __forceinline__ uint32_t s2u(const void* p) {
    uint32_t a;
    asm("{ .reg .u64 t; cvta.to.shared.u64 t, %1; cvt.u32.u64 %0, t; }"
        : "=r"(a) : "l"(p));
    return a;
}
__device__ __forceinline__ uint32_t mapa_(uint32_t a, uint32_t rank) {
    uint32_t p;
    asm("mapa.shared::cluster.u32 %0, %1, %2;" : "=r"(p) : "r"(a), "r"(rank));
    return p;
}
__device__ __forceinline__ void st_remote_u64(uint32_t a, u64 v) {
    asm volatile("st.shared::cluster.u64 [%0], %1;" :: "r"(a), "l"(v) : "memory");
}
__device__ __forceinline__ void arrive_remote(uint32_t a) {
    asm volatile("mbarrier.arrive.release.cluster.shared::cluster.b64 _, [%0];"
                 :: "r"(a) : "memory");
}
__device__ __forceinline__ void mbar_init(uint32_t a, uint32_t cnt) {
    asm volatile("mbarrier.init.shared.b64 [%0], %1;" :: "r"(a), "r"(cnt) : "memory");
}
__device__ __forceinline__ void wait_parity_cl(uint32_t a, uint32_t ph) {
    asm volatile(
        "{ .reg .pred P;\n"
        "L1_%=: mbarrier.try_wait.parity.acquire.cluster.shared::cta.b64 P, [%0], %1;\n"
        "@P bra L2_%=;\n"
        "bra L1_%=;\n"
        "L2_%=: }" :: "r"(a), "r"(ph) : "memory");
}
__device__ __forceinline__ void cluster_sync_() {
    asm volatile("barrier.cluster.arrive.aligned;" ::: "memory");
    asm volatile("barrier.cluster.wait.aligned;" ::: "memory");
}

// ---------------- kernel 0: build contraction tables (2 CTAs, 1/path) -----
__global__ void k_build(const float* g1i, const float* g2i, const float* g3i,
                        const float* g5i, const float* g6i,
                        const float* g1h, const float* g2h, const float* g3h,
                        const float* g5h, const float* g6h,
                        const float* bih, const float* bhh)
{
    __shared__ float G12[1024]; // [i][j][c]
    int tid  = threadIdx.x;     // 1024 threads
    int path = blockIdx.x;      // 0 = ih, 1 = hh

    const float* g1 = path ? g1h : g1i;
    const float* g2 = path ? g2h : g2i;
    const float* g3 = path ? g3h : g3i;
    const float* g5 = path ? g5h : g5i;
    const float* g6 = path ? g6h : g6i;
    float* Gin  = path ? g_Gin_hh  : g_Gin_ih;
    float* G56t = path ? g_G56t_hh : g_G56t_ih;

    { // G12[i][j][c] = sum_a g1[i,a] g2[a,j,c]
        int i = tid >> 7, j = (tid >> 4) & 7, c = tid & 15;
        float s = 0.f;
        #pragma unroll
        for (int a = 0; a < 16; a++)
            s = fmaf(g1[i * 16 + a], g2[a * 128 + j * 16 + c], s);
        G12[tid] = s;
    }
    __syncthreads();
    // Gin[(i,j,k)][d] = sum_c G12[i,j,c] g3[c,k,d]
    for (int o = tid; o < 16384; o += 1024) {
        int row = o >> 4, d = o & 15;
        int i = row >> 7, j = (row >> 4) & 7, k = row & 15;
        float s = 0.f;
        #pragma unroll
        for (int c = 0; c < 16; c++)
            s = fmaf(G12[i * 128 + j * 16 + c], g3[c * 256 + k * 16 + d], s);
        Gin[row * 16 + d] = s;
    }
    // G56t[mp][e] = sum_f g5[e,m,f] g6[f,p]
    for (int o = tid; o < 4096; o += 1024) {
        int e = o >> 8, m = (o >> 4) & 15, p = o & 15;
        float s = 0.f;
        #pragma unroll
        for (int f = 0; f < 16; f++)
            s = fmaf(g5[e * 256 + m * 16 + f], g6[f * 16 + p], s);
        G56t[(m * 16 + p) * 16 + e] = s;
    }
    if (path == 0) { // bias reindexed to [j][gate]
        int j = tid;
        float4 v;
        v.x = bih[j]        + bhh[j];
        v.y = bih[1024 + j] + bhh[1024 + j];
        v.z = bih[2048 + j] + bhh[2048 + j];
        v.w = bih[3072 + j] + bhh[3072 + j];
        ((float4*)g_bias4)[j] = v;
    }
}

// ---------------- kernel 1: precompute ih gates for all (b,t) -------------
__global__ void __launch_bounds__(256) k_pre(const float* __restrict__ x,
                                             const float* __restrict__ g4i)
{
    __shared__ float xs[1024];
    __shared__ float pp[16][17];
    __shared__ float ihp[16];
    __shared__ __align__(16) float A[256]; // [n][e]

    int rb  = blockIdx.x;
    int tid = threadIdx.x;

    ((float4*)xs)[tid] = ((const float4*)(x + (size_t)rb * 1024))[tid];
    __syncthreads();

    { // ihp[d] = sum_j xs[j] * Gin_ih[j][d]
        int d = tid & 15, ch = tid >> 4;
        const float* gp = g_Gin_ih + (ch * 64) * 16 + d;
        const float* xp = xs + ch * 64;
        float s = 0.f;
        #pragma unroll
        for (int u = 0; u < 64; u++) s = fmaf(xp[u], gp[u * 16], s);
        pp[ch][d] = s;
    }
    __syncthreads();
    if (tid < 16) {
        float s = 0.f;
        #pragma unroll
        for (int c2 = 0; c2 < 16; c2++) s += pp[c2][tid];
        ihp[tid] = s;
    }
    __syncthreads();
    { // A[n][e] = sum_d ihp[d] * g4_ih[d][n][e]
        int n = tid >> 4, e = tid & 15;
        float s = 0.f;
        #pragma unroll
        for (int d = 0; d < 16; d++)
            s = fmaf(ihp[d], __ldg(g4i + d * 256 + n * 16 + e), s);
        A[tid] = s;
    }
    __syncthreads();

    // stage2 (packed over e-pairs): mp = tid
    u64 Gp[8];
    {
        const u64* gt = (const u64*)(g_G56t_ih + tid * 16);
        #pragma unroll
        for (int i = 0; i < 8; i++) Gp[i] = gt[i];
    }
    float* outp = g_ihg + (size_t)rb * 4096;
    #pragma unroll
    for (int k = 0; k < 4; k++) {
        int j = k * 256 + tid;
        float4 bv = ((const float4*)g_bias4)[j];
        u64 a0 = 0ull, a1 = 0ull, a2 = 0ull, a3 = 0ull;
        const u64* Ar0 = (const u64*)(A + (0 * 4 + k) * 16);
        const u64* Ar1 = (const u64*)(A + (1 * 4 + k) * 16);
        const u64* Ar2 = (const u64*)(A + (2 * 4 + k) * 16);
        const u64* Ar3 = (const u64*)(A + (3 * 4 + k) * 16);
        #pragma unroll
        for (int i = 0; i < 8; i++) {
            a0 = ffma2(Ar0[i], Gp[i], a0);
            a1 = ffma2(Ar1[i], Gp[i], a1);
            a2 = ffma2(Ar2[i], Gp[i], a2);
            a3 = ffma2(Ar3[i], Gp[i], a3);
        }
        float l0, h0, l1, h1, l2, h2, l3, h3;
        upk2(a0, l0, h0); upk2(a1, l1, h1);
        upk2(a2, l2, h2); upk2(a3, l3, h3);
        float4 v;
        v.x = l0 + h0 + bv.x; v.y = l1 + h1 + bv.y;
        v.z = l2 + h2 + bv.z; v.w = l3 + h3 + bv.w;
        ((float4*)outp)[j] = v;
    }
}

// ---------------- kernel 2: recurrence, 2-CTA cluster per batch -----------
// grid = 128 (64 clusters of 2), 512 threads per CTA. CTA `half` owns hidden
// units [half*512, half*512+512). Per step, partial P[16] is exchanged with
// the peer over DSMEM with double-buffered mbarriers.
__global__ void __launch_bounds__(512, 1) __cluster_dims__(2, 1, 1)
k_rec(const float* __restrict__ g4h, float* __restrict__ out)
{
    __shared__ float g4sh[4096];                 // [d][(n,e)]
    __shared__ __align__(16) float Ash[256];     // [n][e]
    __shared__ __align__(8)  float Psh[16];
    __shared__ u64 ppu[16 * 8];                  // [warp][d-pair]
    __shared__ __align__(8) u64 pbuf[2][8];      // peer's partial lands here
    __shared__ __align__(8) u64 mbar[2];

    int tid  = threadIdx.x;
    int b    = blockIdx.x >> 1;
    int half = blockIdx.x & 1;
    int base = half << 9;                        // 0 or 512
    const unsigned FULL = 0xffffffffu;

    for (int i = tid; i < 4096; i += 512) g4sh[i] = g4h[i];

    // mbarriers: count 8 (each of the 8 sender threads arrives remotely)
    if (tid == 0) {
        mbar_init(s2u(&mbar[0]), 8);
        mbar_init(s2u(&mbar[1]), 8);
    }

    // ---- phase-1 constants: thread = (chunk of 8 local j, d-pair q) ----
    int q     = tid & 7;                         // d-pair: d = 2q, 2q+1
    int ch    = tid >> 3;                        // local j chunk
    int lbase = (ch & 3) * 8;                    // src lane within warp
    u64 Grp[8];
    {
        const float* gbase = g_Gin_hh + (size_t)(base + ch * 8) * 16 + 2 * q;
        #pragma unroll
        for (int u = 0; u < 8; u++)
            Grp[u] = *(const u64*)(gbase + u * 16);
    }
    // ---- stage-2 constants ----
    int mp = tid & 255;
    int nb = (base >> 8) + (tid >> 8);           // global j>>8
    u64 Gp[8];
    {
        const u64* gt = (const u64*)(g_G56t_hh + mp * 16);
        #pragma unroll
        for (int i = 0; i < 8; i++) Gp[i] = gt[i];
    }
    int warp = tid >> 5, lane = tid & 31;
    uint32_t peer = half ^ 1u;
    uint32_t peer_pb0 = mapa_(s2u(&pbuf[0][0]), peer);
    uint32_t peer_pb1 = mapa_(s2u(&pbuf[1][0]), peer);
    uint32_t peer_mb0 = mapa_(s2u(&mbar[0]), peer);
    uint32_t peer_mb1 = mapa_(s2u(&mbar[1]), peer);
    uint32_t my_mb0   = s2u(&mbar[0]);
    uint32_t my_mb1   = s2u(&mbar[1]);

    float h = 0.f, c = 0.f;
    const float* ihp_ptr = g_ihg + (size_t)b * TT * 4096 + (size_t)(base + tid) * 4;
    float* outb = out + (size_t)b * TT * DH + base;

    __syncthreads();
    cluster_sync_();  // mbarriers live in both CTAs before any remote arrive

    for (int t = 0; t < TT; t++) {
        // issue ih-gate load early; consumed after the barriers
        float4 ihg = *(const float4*)(ihp_ptr + (size_t)t * 4096);

        // ---- phase 1: partial P over this CTA's 512 h's (packed pairs) ----
        u64 part = 0ull;
        #pragma unroll
        for (int u = 0; u < 8; u++) {
            float hu = __shfl_sync(FULL, h, lbase + u, 32);
            part = ffma2(pk2(hu, hu), Grp[u], part);
        }
        part = fadd2(part, __shfl_xor_sync(FULL, part, 8));
        part = fadd2(part, __shfl_xor_sync(FULL, part, 16));
        if (lane < 8) ppu[warp * 8 + lane] = part;
        __syncthreads();                               // BAR1

        int slot = t & 1;
        uint32_t ph = (t >> 1) & 1;
        if (tid < 8) {
            u64 s = 0ull;
            #pragma unroll
            for (int w = 0; w < 16; w++) s = fadd2(s, ppu[w * 8 + tid]);
            // ship my partial to the peer, then collect theirs
            uint32_t dst = (slot ? peer_pb1 : peer_pb0) + tid * 8;
            st_remote_u64(dst, s);
            arrive_remote(slot ? peer_mb1 : peer_mb0);
            wait_parity_cl(slot ? my_mb1 : my_mb0, ph);
            u64 tot = fadd2(s, pbuf[slot][tid]);
            float lo, hi; upk2(tot, lo, hi);
            *(float2*)(Psh + 2 * tid) = make_float2(lo, hi);
        }
        __syncthreads();                               // BAR2

        // ---- stage 1: A[n][e] = sum_d P[d] * g4[d][n][e] ----
        if (tid < 256) {
            float s = 0.f;
            #pragma unroll
            for (int d = 0; d < 16; d++)
                s = fmaf(Psh[d], g4sh[d * 256 + tid], s);
            Ash[tid] = s;
        }
        __syncthreads();                               // BAR3

        // ---- stage 2 (packed over e-pairs) ----
        u64 a0 = pk2(ihg.x, 0.f);
        u64 a1 = pk2(ihg.y, 0.f);
        u64 a2 = pk2(ihg.z, 0.f);
        u64 a3 = pk2(ihg.w, 0.f);
        {
            const u64* Ar0 = (const u64*)(Ash + (0 * 4 + nb) * 16);
            const u64* Ar1 = (const u64*)(Ash + (1 * 4 + nb) * 16);
            const u64* Ar2 = (const u64*)(Ash + (2 * 4 + nb) * 16);
            const u64* Ar3 = (const u64*)(Ash + (3 * 4 + nb) * 16);
            #pragma unroll
            for (int i = 0; i < 8; i++) {
                a0 = ffma2(Ar0[i], Gp[i], a0);
                a1 = ffma2(Ar1[i], Gp[i], a1);
                a2 = ffma2(Ar2[i], Gp[i], a2);
                a3 = ffma2(Ar3[i], Gp[i], a3);
            }
        }
        float l0, h0_, l1, h1_, l2, h2_, l3, h3_;
        upk2(a0, l0, h0_); upk2(a1, l1, h1_);
        upk2(a2, l2, h2_); upk2(a3, l3, h3_);
        float gi = l0 + h0_, gf = l1 + h1_, gg = l2 + h2_, go = l3 + h3_;

        // ---- LSTM cell ----
        float si = sigmoidf(gi);
        float sf = sigmoidf(gf);
        float tg = tanhf_(gg);
        float so = sigmoidf(go);
        c = sf * c + si * tg;
        h = so * tanhf_(c);

        outb[(size_t)t * DH + tid] = h;
    }

    // final (h, c) appended after output tensor
    float* hc = out + (size_t)BB * TT * DH;
    hc[b * DH + base + tid] = h;
    hc[(size_t)BB * DH + b * DH + base + tid] = c;

    cluster_sync_();  // keep smem alive until peer's last remote ops land
}

// ---------------- launcher -------------------------------------------------
extern "C" void kernel_launch(void* const* d_in, const int* in_sizes, int n_in,
                              void* d_out, int out_size)
{
    const float* x    = (const float*)d_in[0];
    const float* ih1  = (const float*)d_in[1];
    const float* ih2  = (const float*)d_in[2];
    const float* ih3  = (const float*)d_in[3];
    const float* ih4  = (const float*)d_in[4];
    const float* ih5  = (const float*)d_in[5];
    const float* ih6  = (const float*)d_in[6];
    const float* hh1  = (const float*)d_in[7];
    const float* hh2  = (const float*)d_in[8];
    const float* hh3  = (const float*)d_in[9];
    const float* hh4  = (const float*)d_in[10];
    const float* hh5  = (const float*)d_in[11];
    const float* hh6  = (const float*)d_in[12];
    const float* bih  = (const float*)d_in[13];
    const float* bhh  = (const float*)d_in[14];
    float* out = (float*)d_out;

    k_build<<<2, 1024>>>(ih1, ih2, ih3, ih5, ih6,
                         hh1, hh2, hh3, hh5, hh6, bih, bhh);
    k_pre<<<BB * TT, 256>>>(x, ih4);
    k_rec<<<BB * 2, 512>>>(hh4, out);
}

// round 5
// speedup vs baseline: 1.2854x; 1.2854x over previous
#include <cuda_runtime.h>
#include <cstdint>

#define BB   64
#define TT   512
#define DH   1024

// ---------------- device scratch (static, allocation-free) ----------------
__device__ float g_Gin_ih[1024 * 16];    // [j][d]
__device__ float g_Gin_hh[1024 * 16];    // [j][d]
__device__ float g_G56t_ih[256 * 16];    // [mp][e]  (transposed)
__device__ float g_G56t_hh[256 * 16];    // [mp][e]
__device__ float g_bias4[4096];          // [j][gate]
__device__ float g_ihg[(size_t)BB * TT * 4096]; // [b][t][j][gate]

typedef unsigned long long u64;

// ---------------- packed f32x2 helpers ------------------------------------
__device__ __forceinline__ u64 pk2(float lo, float hi) {
    u64 r; asm("mov.b64 %0, {%1,%2};" : "=l"(r) : "f"(lo), "f"(hi)); return r;
}
__device__ __forceinline__ void upk2(u64 v, float& lo, float& hi) {
    asm("mov.b64 {%0,%1}, %2;" : "=f"(lo), "=f"(hi) : "l"(v));
}
__device__ __forceinline__ u64 ffma2(u64 a, u64 b, u64 c) {
    u64 d; asm("fma.rn.f32x2 %0, %1, %2, %3;" : "=l"(d) : "l"(a), "l"(b), "l"(c));
    return d;
}
__device__ __forceinline__ u64 fadd2(u64 a, u64 b) {
    u64 d; asm("add.rn.f32x2 %0, %1, %2;" : "=l"(d) : "l"(a), "l"(b));
    return d;
}

// ---------------- activations ---------------------------------------------
// HW tanh (sm_75+): 1 MUFU op, abs err ~5e-4
__device__ __forceinline__ float htanh(float x) {
    float y; asm("tanh.approx.f32 %0, %1;" : "=f"(y) : "f"(x)); return y;
}
__device__ __forceinline__ float hsig(float x) {
    return fmaf(0.5f, htanh(0.5f * x), 0.5f);
}
// accurate ex2/rcp pair kept for k_pre-free paths (unused in hot loop)
__device__ __forceinline__ float fexp2(float x) {
    float y; asm("ex2.approx.f32 %0, %1;" : "=f"(y) : "f"(x)); return y;
}

// ---------------- kernel 0: build contraction tables (2 CTAs, 1/path) -----
__global__ void k_build(const float* g1i, const float* g2i, const float* g3i,
                        const float* g5i, const float* g6i,
                        const float* g1h, const float* g2h, const float* g3h,
                        const float* g5h, const float* g6h,
                        const float* bih, const float* bhh)
{
    __shared__ float G12[1024]; // [i][j][c]
    int tid  = threadIdx.x;     // 1024 threads
    int path = blockIdx.x;      // 0 = ih, 1 = hh

    const float* g1 = path ? g1h : g1i;
    const float* g2 = path ? g2h : g2i;
    const float* g3 = path ? g3h : g3i;
    const float* g5 = path ? g5h : g5i;
    const float* g6 = path ? g6h : g6i;
    float* Gin  = path ? g_Gin_hh  : g_Gin_ih;
    float* G56t = path ? g_G56t_hh : g_G56t_ih;

    { // G12[i][j][c] = sum_a g1[i,a] g2[a,j,c]
        int i = tid >> 7, j = (tid >> 4) & 7, c = tid & 15;
        float s = 0.f;
        #pragma unroll
        for (int a = 0; a < 16; a++)
            s = fmaf(g1[i * 16 + a], g2[a * 128 + j * 16 + c], s);
        G12[tid] = s;
    }
    __syncthreads();
    // Gin[(i,j,k)][d] = sum_c G12[i,j,c] g3[c,k,d]
    for (int o = tid; o < 16384; o += 1024) {
        int row = o >> 4, d = o & 15;
        int i = row >> 7, j = (row >> 4) & 7, k = row & 15;
        float s = 0.f;
        #pragma unroll
        for (int c = 0; c < 16; c++)
            s = fmaf(G12[i * 128 + j * 16 + c], g3[c * 256 + k * 16 + d], s);
        Gin[row * 16 + d] = s;
    }
    // G56t[mp][e] = sum_f g5[e,m,f] g6[f,p]
    for (int o = tid; o < 4096; o += 1024) {
        int e = o >> 8, m = (o >> 4) & 15, p = o & 15;
        float s = 0.f;
        #pragma unroll
        for (int f = 0; f < 16; f++)
            s = fmaf(g5[e * 256 + m * 16 + f], g6[f * 16 + p], s);
        G56t[(m * 16 + p) * 16 + e] = s;
    }
    if (path == 0) { // bias reindexed to [j][gate]
        int j = tid;
        float4 v;
        v.x = bih[j]        + bhh[j];
        v.y = bih[1024 + j] + bhh[1024 + j];
        v.z = bih[2048 + j] + bhh[2048 + j];
        v.w = bih[3072 + j] + bhh[3072 + j];
        ((float4*)g_bias4)[j] = v;
    }
}

// ---------------- kernel 1: precompute ih gates for all (b,t) -------------
__global__ void __launch_bounds__(256) k_pre(const float* __restrict__ x,
                                             const float* __restrict__ g4i)
{
    __shared__ float xs[1024];
    __shared__ float pp[16][17];
    __shared__ float ihp[16];
    __shared__ __align__(16) float A[256]; // [n][e]

    int rb  = blockIdx.x;
    int tid = threadIdx.x;

    ((float4*)xs)[tid] = ((const float4*)(x + (size_t)rb * 1024))[tid];
    __syncthreads();

    { // ihp[d] = sum_j xs[j] * Gin_ih[j][d]
        int d = tid & 15, ch = tid >> 4;
        const float* gp = g_Gin_ih + (ch * 64) * 16 + d;
        const float* xp = xs + ch * 64;
        float s = 0.f;
        #pragma unroll
        for (int u = 0; u < 64; u++) s = fmaf(xp[u], gp[u * 16], s);
        pp[ch][d] = s;
    }
    __syncthreads();
    if (tid < 16) {
        float s = 0.f;
        #pragma unroll
        for (int c2 = 0; c2 < 16; c2++) s += pp[c2][tid];
        ihp[tid] = s;
    }
    __syncthreads();
    { // A[n][e] = sum_d ihp[d] * g4_ih[d][n][e]
        int n = tid >> 4, e = tid & 15;
        float s = 0.f;
        #pragma unroll
        for (int d = 0; d < 16; d++)
            s = fmaf(ihp[d], __ldg(g4i + d * 256 + n * 16 + e), s);
        A[tid] = s;
    }
    __syncthreads();

    // stage2 (packed over e-pairs): mp = tid
    u64 Gp[8];
    {
        const u64* gt = (const u64*)(g_G56t_ih + tid * 16);
        #pragma unroll
        for (int i = 0; i < 8; i++) Gp[i] = gt[i];
    }
    float* outp = g_ihg + (size_t)rb * 4096;
    #pragma unroll
    for (int k = 0; k < 4; k++) {
        int j = k * 256 + tid;
        float4 bv = ((const float4*)g_bias4)[j];
        u64 a0 = 0ull, a1 = 0ull, a2 = 0ull, a3 = 0ull;
        const u64* Ar0 = (const u64*)(A + (0 * 4 + k) * 16);
        const u64* Ar1 = (const u64*)(A + (1 * 4 + k) * 16);
        const u64* Ar2 = (const u64*)(A + (2 * 4 + k) * 16);
        const u64* Ar3 = (const u64*)(A + (3 * 4 + k) * 16);
        #pragma unroll
        for (int i = 0; i < 8; i++) {
            a0 = ffma2(Ar0[i], Gp[i], a0);
            a1 = ffma2(Ar1[i], Gp[i], a1);
            a2 = ffma2(Ar2[i], Gp[i], a2);
            a3 = ffma2(Ar3[i], Gp[i], a3);
        }
        float l0, h0, l1, h1, l2, h2, l3, h3;
        upk2(a0, l0, h0); upk2(a1, l1, h1);
        upk2(a2, l2, h2); upk2(a3, l3, h3);
        float4 v;
        v.x = l0 + h0 + bv.x; v.y = l1 + h1 + bv.y;
        v.z = l2 + h2 + bv.z; v.w = l3 + h3 + bv.w;
        ((float4*)outp)[j] = v;
    }
}

// ---------------- kernel 2: recurrence ------------------------------------
// 64 CTAs x 512 threads; thread owns hidden units j1=tid and j2=tid+512.
// Register budget per thread (cap 128 at 512 thr/CTA): Grp 32, Gp 16,
// ihg carry 16, accums 16, state 4, misc ~20  ->  no spills.
__global__ void __launch_bounds__(512, 1) k_rec(const float* __restrict__ g4h,
                                                float* __restrict__ out)
{
    __shared__ u64 g4p[8][256];                  // paired g4: (d=2q, 2q+1)
    __shared__ __align__(16) float Ash[256];     // [n][e]
    __shared__ __align__(16) u64 Psh2[8];        // P packed in d-pairs
    __shared__ u64 ppu[16][8];                   // [warp][d-pair]

    int tid = threadIdx.x;
    int b   = blockIdx.x;
    const unsigned FULL = 0xffffffffu;

    // build paired g4 in smem: g4p[q][col] = (g4[2q][col], g4[2q+1][col])
    for (int i = tid; i < 2048; i += 512) {
        int q = i >> 8, col = i & 255;
        g4p[q][col] = pk2(g4h[(2 * q) * 256 + col], g4h[(2 * q + 1) * 256 + col]);
    }

    // ---- phase-1 constants: thread = (j-chunk ch, d-pair q) ----
    int q     = tid & 7;                 // d-pair
    int ch    = tid >> 3;                // chunk 0..63 (8 j's each), + chunk ch+64
    int lbase = (ch & 3) * 8;            // source lanes within this warp
    u64 Grp1[8], Grp2[8];
    {
        const float* gb1 = g_Gin_hh + (size_t)(ch * 8) * 16 + 2 * q;
        const float* gb2 = gb1 + 512 * 16;
        #pragma unroll
        for (int u = 0; u < 8; u++) {
            Grp1[u] = *(const u64*)(gb1 + u * 16);
            Grp2[u] = *(const u64*)(gb2 + u * 16);
        }
    }
    // ---- stage-2 constants ----
    int mp  = tid & 255;
    int nb1 = tid >> 8;                  // 0..1  (j1 = tid)
    int nb2 = nb1 + 2;                   // 2..3  (j2 = tid + 512)
    u64 Gp[8];
    {
        const u64* gt = (const u64*)(g_G56t_hh + mp * 16);
        #pragma unroll
        for (int i = 0; i < 8; i++) Gp[i] = gt[i];
    }
    int warp = tid >> 5, lane = tid & 31;

    float h1 = 0.f, c1 = 0.f, h2 = 0.f, c2 = 0.f;
    const float* ihp1 = g_ihg + (size_t)b * TT * 4096 + (size_t)tid * 4;
    const float* ihp2 = ihp1 + 512 * 4;
    float* outb = out + (size_t)b * TT * DH;

    float4 ihg1 = *(const float4*)ihp1;          // t = 0
    float4 ihg2 = *(const float4*)ihp2;

    __syncthreads();

    for (int t = 0; t < TT; t++) {
        // ---- phase 1: partial P over 16 j's (two chunks), packed pairs ----
        u64 part = 0ull;
        #pragma unroll
        for (int u = 0; u < 8; u++) {
            float a = __shfl_sync(FULL, h1, lbase + u, 32);
            part = ffma2(pk2(a, a), Grp1[u], part);
        }
        #pragma unroll
        for (int u = 0; u < 8; u++) {
            float a = __shfl_sync(FULL, h2, lbase + u, 32);
            part = ffma2(pk2(a, a), Grp2[u], part);
        }
        part = fadd2(part, __shfl_xor_sync(FULL, part, 8));
        part = fadd2(part, __shfl_xor_sync(FULL, part, 16));
        if (lane < 8) ppu[warp][lane] = part;

        // prefetch next step's ih gates (covered by 3 barriers + 2 sections)
        float4 ihg1n, ihg2n;
        if (t < TT - 1) {
            ihg1n = *(const float4*)(ihp1 + (size_t)(t + 1) * 4096);
            ihg2n = *(const float4*)(ihp2 + (size_t)(t + 1) * 4096);
        } else {
            ihg1n = make_float4(0.f, 0.f, 0.f, 0.f);
            ihg2n = ihg1n;
        }
        __syncthreads();                               // BAR1

        // ---- reduce 16 warp-partials -> P (16 threads, 2-level) ----
        if (tid < 16) {
            int qq = tid & 7, hf = tid >> 3;
            u64 s = ppu[hf * 8 + 0][qq];
            #pragma unroll
            for (int w = 1; w < 8; w++) s = fadd2(s, ppu[hf * 8 + w][qq]);
            s = fadd2(s, __shfl_xor_sync(0xffffu, s, 8, 16));
            if (tid < 8) Psh2[qq] = s;
        }
        __syncthreads();                               // BAR2

        // ---- stage 1: A[col] = sum_q <Psh2[q], g4p[q][col]> ----
        if (tid < 256) {
            u64 acc = 0ull;
            #pragma unroll
            for (int qi = 0; qi < 8; qi++)
                acc = ffma2(Psh2[qi], g4p[qi][tid], acc);
            float lo, hi; upk2(acc, lo, hi);
            Ash[tid] = lo + hi;
        }
        __syncthreads();                               // BAR3

        // ---- stage 2 (packed over e-pairs), both hidden units ----
        u64 a0 = pk2(ihg1.x, 0.f), a1 = pk2(ihg1.y, 0.f);
        u64 a2 = pk2(ihg1.z, 0.f), a3 = pk2(ihg1.w, 0.f);
        u64 b0 = pk2(ihg2.x, 0.f), b1 = pk2(ihg2.y, 0.f);
        u64 b2 = pk2(ihg2.z, 0.f), b3 = pk2(ihg2.w, 0.f);
        {
            const u64* Ar0 = (const u64*)(Ash + (0 * 4 + nb1) * 16);
            const u64* Ar1 = (const u64*)(Ash + (1 * 4 + nb1) * 16);
            const u64* Ar2 = (const u64*)(Ash + (2 * 4 + nb1) * 16);
            const u64* Ar3 = (const u64*)(Ash + (3 * 4 + nb1) * 16);
            const u64* Br0 = (const u64*)(Ash + (0 * 4 + nb2) * 16);
            const u64* Br1 = (const u64*)(Ash + (1 * 4 + nb2) * 16);
            const u64* Br2 = (const u64*)(Ash + (2 * 4 + nb2) * 16);
            const u64* Br3 = (const u64*)(Ash + (3 * 4 + nb2) * 16);
            #pragma unroll
            for (int i = 0; i < 8; i++) {
                u64 g = Gp[i];
                a0 = ffma2(Ar0[i], g, a0);
                a1 = ffma2(Ar1[i], g, a1);
                a2 = ffma2(Ar2[i], g, a2);
                a3 = ffma2(Ar3[i], g, a3);
                b0 = ffma2(Br0[i], g, b0);
                b1 = ffma2(Br1[i], g, b1);
                b2 = ffma2(Br2[i], g, b2);
                b3 = ffma2(Br3[i], g, b3);
            }
        }
        float xlo, xhi, gi1, gf1, gg1, go1, gi2, gf2, gg2, go2;
        upk2(a0, xlo, xhi); gi1 = xlo + xhi;
        upk2(a1, xlo, xhi); gf1 = xlo + xhi;
        upk2(a2, xlo, xhi); gg1 = xlo + xhi;
        upk2(a3, xlo, xhi); go1 = xlo + xhi;
        upk2(b0, xlo, xhi); gi2 = xlo + xhi;
        upk2(b1, xlo, xhi); gf2 = xlo + xhi;
        upk2(b2, xlo, xhi); gg2 = xlo + xhi;
        upk2(b3, xlo, xhi); go2 = xlo + xhi;

        // ---- LSTM cell (HW tanh: 4 MUFU per hidden unit) ----
        c1 = hsig(gf1) * c1 + hsig(gi1) * htanh(gg1);
        h1 = hsig(go1) * htanh(c1);
        c2 = hsig(gf2) * c2 + hsig(gi2) * htanh(gg2);
        h2 = hsig(go2) * htanh(c2);

        outb[(size_t)t * DH + tid]       = h1;
        outb[(size_t)t * DH + tid + 512] = h2;
        ihg1 = ihg1n; ihg2 = ihg2n;
    }

    // final (h, c) appended after output tensor
    float* hc = out + (size_t)BB * TT * DH;
    hc[b * DH + tid]       = h1;
    hc[b * DH + tid + 512] = h2;
    hc[(size_t)BB * DH + b * DH + tid]       = c1;
    hc[(size_t)BB * DH + b * DH + tid + 512] = c2;
}

// ---------------- launcher -------------------------------------------------
extern "C" void kernel_launch(void* const* d_in, const int* in_sizes, int n_in,
                              void* d_out, int out_size)
{
    const float* x    = (const float*)d_in[0];
    const float* ih1  = (const float*)d_in[1];
    const float* ih2  = (const float*)d_in[2];
    const float* ih3  = (const float*)d_in[3];
    const float* ih4  = (const float*)d_in[4];
    const float* ih5  = (const float*)d_in[5];
    const float* ih6  = (const float*)d_in[6];
    const float* hh1  = (const float*)d_in[7];
    const float* hh2  = (const float*)d_in[8];
    const float* hh3  = (const float*)d_in[9];
    const float* hh4  = (const float*)d_in[10];
    const float* hh5  = (const float*)d_in[11];
    const float* hh6  = (const float*)d_in[12];
    const float* bih  = (const float*)d_in[13];
    const float* bhh  = (const float*)d_in[14];
    float* out = (float*)d_out;

    k_build<<<2, 1024>>>(ih1, ih2, ih3, ih5, ih6,
                         hh1, hh2, hh3, hh5, hh6, bih, bhh);
    k_pre<<<BB * TT, 256>>>(x, ih4);
    k_rec<<<BB, 512>>>(hh4, out);
}

// round 6
// speedup vs baseline: 1.3124x; 1.0210x over previous
#include <cuda_runtime.h>
#include <cstdint>

#define BB   64
#define TT   512
#define DH   1024

// ---------------- device scratch (static, allocation-free) ----------------
__device__ float g_Gin_ih[1024 * 16];    // [j][d]
__device__ float g_Gin_hh[1024 * 16];    // [j][d]
__device__ float g_G56t_ih[256 * 16];    // [mp][e]  (transposed)
__device__ float g_G56t_hh[256 * 16];    // [mp][e]
__device__ float g_bias4[4096];          // [j][gate]
__device__ float g_ihg[(size_t)BB * TT * 4096]; // [b][t][j][gate]

typedef unsigned long long u64;

// ---------------- packed f32x2 helpers ------------------------------------
__device__ __forceinline__ u64 pk2(float lo, float hi) {
    u64 r; asm("mov.b64 %0, {%1,%2};" : "=l"(r) : "f"(lo), "f"(hi)); return r;
}
__device__ __forceinline__ void upk2(u64 v, float& lo, float& hi) {
    asm("mov.b64 {%0,%1}, %2;" : "=f"(lo), "=f"(hi) : "l"(v));
}
__device__ __forceinline__ u64 ffma2(u64 a, u64 b, u64 c) {
    u64 d; asm("fma.rn.f32x2 %0, %1, %2, %3;" : "=l"(d) : "l"(a), "l"(b), "l"(c));
    return d;
}
__device__ __forceinline__ u64 fadd2(u64 a, u64 b) {
    u64 d; asm("add.rn.f32x2 %0, %1, %2;" : "=l"(d) : "l"(a), "l"(b));
    return d;
}

// ---------------- activations ---------------------------------------------
__device__ __forceinline__ float htanh(float x) {
    float y; asm("tanh.approx.f32 %0, %1;" : "=f"(y) : "f"(x)); return y;
}
__device__ __forceinline__ float hsig(float x) {
    return fmaf(0.5f, htanh(0.5f * x), 0.5f);
}

// ---------------- kernel 0: build contraction tables (2 CTAs, 1/path) -----
__global__ void k_build(const float* g1i, const float* g2i, const float* g3i,
                        const float* g5i, const float* g6i,
                        const float* g1h, const float* g2h, const float* g3h,
                        const float* g5h, const float* g6h,
                        const float* bih, const float* bhh)
{
    __shared__ float G12[1024]; // [i][j][c]
    int tid  = threadIdx.x;     // 1024 threads
    int path = blockIdx.x;      // 0 = ih, 1 = hh

    const float* g1 = path ? g1h : g1i;
    const float* g2 = path ? g2h : g2i;
    const float* g3 = path ? g3h : g3i;
    const float* g5 = path ? g5h : g5i;
    const float* g6 = path ? g6h : g6i;
    float* Gin  = path ? g_Gin_hh  : g_Gin_ih;
    float* G56t = path ? g_G56t_hh : g_G56t_ih;

    { // G12[i][j][c] = sum_a g1[i,a] g2[a,j,c]
        int i = tid >> 7, j = (tid >> 4) & 7, c = tid & 15;
        float s = 0.f;
        #pragma unroll
        for (int a = 0; a < 16; a++)
            s = fmaf(g1[i * 16 + a], g2[a * 128 + j * 16 + c], s);
        G12[tid] = s;
    }
    __syncthreads();
    // Gin[(i,j,k)][d] = sum_c G12[i,j,c] g3[c,k,d]
    for (int o = tid; o < 16384; o += 1024) {
        int row = o >> 4, d = o & 15;
        int i = row >> 7, j = (row >> 4) & 7, k = row & 15;
        float s = 0.f;
        #pragma unroll
        for (int c = 0; c < 16; c++)
            s = fmaf(G12[i * 128 + j * 16 + c], g3[c * 256 + k * 16 + d], s);
        Gin[row * 16 + d] = s;
    }
    // G56t[mp][e] = sum_f g5[e,m,f] g6[f,p]
    for (int o = tid; o < 4096; o += 1024) {
        int e = o >> 8, m = (o >> 4) & 15, p = o & 15;
        float s = 0.f;
        #pragma unroll
        for (int f = 0; f < 16; f++)
            s = fmaf(g5[e * 256 + m * 16 + f], g6[f * 16 + p], s);
        G56t[(m * 16 + p) * 16 + e] = s;
    }
    if (path == 0) { // bias reindexed to [j][gate]
        int j = tid;
        float4 v;
        v.x = bih[j]        + bhh[j];
        v.y = bih[1024 + j] + bhh[1024 + j];
        v.z = bih[2048 + j] + bhh[2048 + j];
        v.w = bih[3072 + j] + bhh[3072 + j];
        ((float4*)g_bias4)[j] = v;
    }
}

// ---------------- kernel 1: precompute ih gates for all (b,t) -------------
__global__ void __launch_bounds__(256) k_pre(const float* __restrict__ x,
                                             const float* __restrict__ g4i)
{
    __shared__ float xs[1024];
    __shared__ float pp[16][17];
    __shared__ float ihp[16];
    __shared__ __align__(16) float A[256]; // [n][e]

    int rb  = blockIdx.x;
    int tid = threadIdx.x;

    ((float4*)xs)[tid] = ((const float4*)(x + (size_t)rb * 1024))[tid];
    __syncthreads();

    { // ihp[d] = sum_j xs[j] * Gin_ih[j][d]
        int d = tid & 15, ch = tid >> 4;
        const float* gp = g_Gin_ih + (ch * 64) * 16 + d;
        const float* xp = xs + ch * 64;
        float s = 0.f;
        #pragma unroll
        for (int u = 0; u < 64; u++) s = fmaf(xp[u], gp[u * 16], s);
        pp[ch][d] = s;
    }
    __syncthreads();
    if (tid < 16) {
        float s = 0.f;
        #pragma unroll
        for (int c2 = 0; c2 < 16; c2++) s += pp[c2][tid];
        ihp[tid] = s;
    }
    __syncthreads();
    { // A[n][e] = sum_d ihp[d] * g4_ih[d][n][e]
        int n = tid >> 4, e = tid & 15;
        float s = 0.f;
        #pragma unroll
        for (int d = 0; d < 16; d++)
            s = fmaf(ihp[d], __ldg(g4i + d * 256 + n * 16 + e), s);
        A[tid] = s;
    }
    __syncthreads();

    // stage2 (packed over e-pairs): mp = tid
    u64 Gp[8];
    {
        const u64* gt = (const u64*)(g_G56t_ih + tid * 16);
        #pragma unroll
        for (int i = 0; i < 8; i++) Gp[i] = gt[i];
    }
    float* outp = g_ihg + (size_t)rb * 4096;
    #pragma unroll
    for (int k = 0; k < 4; k++) {
        int j = k * 256 + tid;
        float4 bv = ((const float4*)g_bias4)[j];
        u64 a0 = 0ull, a1 = 0ull, a2 = 0ull, a3 = 0ull;
        const ulonglong2* Ar0 = (const ulonglong2*)(A + (0 * 4 + k) * 16);
        const ulonglong2* Ar1 = (const ulonglong2*)(A + (1 * 4 + k) * 16);
        const ulonglong2* Ar2 = (const ulonglong2*)(A + (2 * 4 + k) * 16);
        const ulonglong2* Ar3 = (const ulonglong2*)(A + (3 * 4 + k) * 16);
        #pragma unroll
        for (int i = 0; i < 4; i++) {
            ulonglong2 w0 = Ar0[i], w1 = Ar1[i], w2 = Ar2[i], w3 = Ar3[i];
            a0 = ffma2(w0.x, Gp[2 * i], a0); a0 = ffma2(w0.y, Gp[2 * i + 1], a0);
            a1 = ffma2(w1.x, Gp[2 * i], a1); a1 = ffma2(w1.y, Gp[2 * i + 1], a1);
            a2 = ffma2(w2.x, Gp[2 * i], a2); a2 = ffma2(w2.y, Gp[2 * i + 1], a2);
            a3 = ffma2(w3.x, Gp[2 * i], a3); a3 = ffma2(w3.y, Gp[2 * i + 1], a3);
        }
        float l0, h0, l1, h1, l2, h2, l3, h3;
        upk2(a0, l0, h0); upk2(a1, l1, h1);
        upk2(a2, l2, h2); upk2(a3, l3, h3);
        float4 v;
        v.x = l0 + h0 + bv.x; v.y = l1 + h1 + bv.y;
        v.z = l2 + h2 + bv.z; v.w = l3 + h3 + bv.w;
        ((float4*)outp)[j] = v;
    }
}

// ---------------- kernel 2: recurrence ------------------------------------
// 64 CTAs x 512 threads; thread owns hidden units j1=tid, j2=tid+512.
// Two barriers per step: phase1 -> [BAR1] -> fused reduce+stage1 (warps 0-7,
// P broadcast via shfl, no smem round-trip) -> [BAR2] -> stage2 + cell.
__global__ void __launch_bounds__(512, 1) k_rec(const float* __restrict__ g4h,
                                                float* __restrict__ out)
{
    __shared__ u64 g4p[8][256];                  // paired g4: (d=2q, 2q+1)
    __shared__ __align__(16) float Ash[256];     // [n][e]
    __shared__ u64 ppu[16][8];                   // [warp][d-pair]

    int tid = threadIdx.x;
    int b   = blockIdx.x;
    const unsigned FULL = 0xffffffffu;

    // build paired g4 in smem: g4p[q][col] = (g4[2q][col], g4[2q+1][col])
    for (int i = tid; i < 2048; i += 512) {
        int q = i >> 8, col = i & 255;
        g4p[q][col] = pk2(g4h[(2 * q) * 256 + col], g4h[(2 * q + 1) * 256 + col]);
    }

    // ---- phase-1 constants: thread = (j-chunk ch, d-pair q) ----
    int q     = tid & 7;                 // d-pair
    int ch    = tid >> 3;                // chunk 0..63 (8 j's), + chunk ch+64
    int lbase = (ch & 3) * 8;            // source lanes within this warp
    u64 Grp1[8], Grp2[8];
    {
        const float* gb1 = g_Gin_hh + (size_t)(ch * 8) * 16 + 2 * q;
        const float* gb2 = gb1 + 512 * 16;
        #pragma unroll
        for (int u = 0; u < 8; u++) {
            Grp1[u] = *(const u64*)(gb1 + u * 16);
            Grp2[u] = *(const u64*)(gb2 + u * 16);
        }
    }
    // ---- stage-2 constants ----
    int mp  = tid & 255;
    int nb1 = tid >> 8;                  // 0..1  (j1 = tid)
    int nb2 = nb1 + 2;                   // 2..3  (j2 = tid + 512)
    u64 Gp[8];
    {
        const u64* gt = (const u64*)(g_G56t_hh + mp * 16);
        #pragma unroll
        for (int i = 0; i < 8; i++) Gp[i] = gt[i];
    }
    int warp = tid >> 5, lane = tid & 31;

    float h1 = 0.f, c1 = 0.f, h2 = 0.f, c2 = 0.f;
    const float* ihp1 = g_ihg + (size_t)b * TT * 4096 + (size_t)tid * 4;
    const float* ihp2 = ihp1 + 512 * 4;
    float* outb = out + (size_t)b * TT * DH;

    float4 ihg1 = *(const float4*)ihp1;          // t = 0
    float4 ihg2 = *(const float4*)ihp2;

    __syncthreads();

    for (int t = 0; t < TT; t++) {
        // ---- phase 1: partial P over 16 j's (two chunks), packed pairs ----
        u64 part = 0ull;
        #pragma unroll
        for (int u = 0; u < 8; u++) {
            float a = __shfl_sync(FULL, h1, lbase + u, 32);
            part = ffma2(pk2(a, a), Grp1[u], part);
        }
        #pragma unroll
        for (int u = 0; u < 8; u++) {
            float a = __shfl_sync(FULL, h2, lbase + u, 32);
            part = ffma2(pk2(a, a), Grp2[u], part);
        }
        part = fadd2(part, __shfl_xor_sync(FULL, part, 8));
        part = fadd2(part, __shfl_xor_sync(FULL, part, 16));
        if (lane < 8) ppu[warp][lane] = part;

        // prefetch next step's ih gates (clamped, branch-free)
        int tn = (t + 1 < TT) ? (t + 1) : t;
        float4 ihg1n = *(const float4*)(ihp1 + (size_t)tn * 4096);
        float4 ihg2n = *(const float4*)(ihp2 + (size_t)tn * 4096);
        __syncthreads();                               // BAR1

        // ---- fused reduce + stage 1 (warps 0-7; col = tid) ----
        if (tid < 256) {
            int w0 = lane >> 3, qq = lane & 7;
            u64 s = fadd2(fadd2(ppu[w0][qq], ppu[w0 + 4][qq]),
                          fadd2(ppu[w0 + 8][qq], ppu[w0 + 12][qq]));
            s = fadd2(s, __shfl_xor_sync(FULL, s, 8));
            s = fadd2(s, __shfl_xor_sync(FULL, s, 16));
            // s now holds P-pair[lane&7]; feed stage1 via idx-shfl broadcast
            u64 acc = 0ull;
            #pragma unroll
            for (int qi = 0; qi < 8; qi++) {
                u64 pq = __shfl_sync(FULL, s, qi, 32);
                acc = ffma2(pq, g4p[qi][tid], acc);
            }
            float lo, hi; upk2(acc, lo, hi);
            Ash[tid] = lo + hi;
        }
        __syncthreads();                               // BAR2

        // ---- stage 2 (LDS.128 loads, packed over e-pairs) ----
        u64 a0 = pk2(ihg1.x, 0.f), a1 = pk2(ihg1.y, 0.f);
        u64 a2 = pk2(ihg1.z, 0.f), a3 = pk2(ihg1.w, 0.f);
        u64 b0 = pk2(ihg2.x, 0.f), b1 = pk2(ihg2.y, 0.f);
        u64 b2 = pk2(ihg2.z, 0.f), b3 = pk2(ihg2.w, 0.f);
        {
            const ulonglong2* Ar0 = (const ulonglong2*)(Ash + (0 * 4 + nb1) * 16);
            const ulonglong2* Ar1 = (const ulonglong2*)(Ash + (1 * 4 + nb1) * 16);
            const ulonglong2* Ar2 = (const ulonglong2*)(Ash + (2 * 4 + nb1) * 16);
            const ulonglong2* Ar3 = (const ulonglong2*)(Ash + (3 * 4 + nb1) * 16);
            const ulonglong2* Br0 = (const ulonglong2*)(Ash + (0 * 4 + nb2) * 16);
            const ulonglong2* Br1 = (const ulonglong2*)(Ash + (1 * 4 + nb2) * 16);
            const ulonglong2* Br2 = (const ulonglong2*)(Ash + (2 * 4 + nb2) * 16);
            const ulonglong2* Br3 = (const ulonglong2*)(Ash + (3 * 4 + nb2) * 16);
            #pragma unroll
            for (int i = 0; i < 4; i++) {
                u64 gA = Gp[2 * i], gB = Gp[2 * i + 1];
                ulonglong2 w;
                w = Ar0[i]; a0 = ffma2(w.x, gA, a0); a0 = ffma2(w.y, gB, a0);
                w = Ar1[i]; a1 = ffma2(w.x, gA, a1); a1 = ffma2(w.y, gB, a1);
                w = Ar2[i]; a2 = ffma2(w.x, gA, a2); a2 = ffma2(w.y, gB, a2);
                w = Ar3[i]; a3 = ffma2(w.x, gA, a3); a3 = ffma2(w.y, gB, a3);
                w = Br0[i]; b0 = ffma2(w.x, gA, b0); b0 = ffma2(w.y, gB, b0);
                w = Br1[i]; b1 = ffma2(w.x, gA, b1); b1 = ffma2(w.y, gB, b1);
                w = Br2[i]; b2 = ffma2(w.x, gA, b2); b2 = ffma2(w.y, gB, b2);
                w = Br3[i]; b3 = ffma2(w.x, gA, b3); b3 = ffma2(w.y, gB, b3);
            }
        }
        float xlo, xhi, gi1, gf1, gg1, go1, gi2, gf2, gg2, go2;
        upk2(a0, xlo, xhi); gi1 = xlo + xhi;
        upk2(a1, xlo, xhi); gf1 = xlo + xhi;
        upk2(a2, xlo, xhi); gg1 = xlo + xhi;
        upk2(a3, xlo, xhi); go1 = xlo + xhi;
        upk2(b0, xlo, xhi); gi2 = xlo + xhi;
        upk2(b1, xlo, xhi); gf2 = xlo + xhi;
        upk2(b2, xlo, xhi); gg2 = xlo + xhi;
        upk2(b3, xlo, xhi); go2 = xlo + xhi;

        // ---- LSTM cell (HW tanh) ----
        c1 = hsig(gf1) * c1 + hsig(gi1) * htanh(gg1);
        h1 = hsig(go1) * htanh(c1);
        c2 = hsig(gf2) * c2 + hsig(gi2) * htanh(gg2);
        h2 = hsig(go2) * htanh(c2);

        outb[(size_t)t * DH + tid]       = h1;
        outb[(size_t)t * DH + tid + 512] = h2;
        ihg1 = ihg1n; ihg2 = ihg2n;
    }

    // final (h, c) appended after output tensor
    float* hc = out + (size_t)BB * TT * DH;
    hc[b * DH + tid]       = h1;
    hc[b * DH + tid + 512] = h2;
    hc[(size_t)BB * DH + b * DH + tid]       = c1;
    hc[(size_t)BB * DH + b * DH + tid + 512] = c2;
}

// ---------------- launcher -------------------------------------------------
extern "C" void kernel_launch(void* const* d_in, const int* in_sizes, int n_in,
                              void* d_out, int out_size)
{
    const float* x    = (const float*)d_in[0];
    const float* ih1  = (const float*)d_in[1];
    const float* ih2  = (const float*)d_in[2];
    const float* ih3  = (const float*)d_in[3];
    const float* ih4  = (const float*)d_in[4];
    const float* ih5  = (const float*)d_in[5];
    const float* ih6  = (const float*)d_in[6];
    const float* hh1  = (const float*)d_in[7];
    const float* hh2  = (const float*)d_in[8];
    const float* hh3  = (const float*)d_in[9];
    const float* hh4  = (const float*)d_in[10];
    const float* hh5  = (const float*)d_in[11];
    const float* hh6  = (const float*)d_in[12];
    const float* bih  = (const float*)d_in[13];
    const float* bhh  = (const float*)d_in[14];
    float* out = (float*)d_out;

    k_build<<<2, 1024>>>(ih1, ih2, ih3, ih5, ih6,
                         hh1, hh2, hh3, hh5, hh6, bih, bhh);
    k_pre<<<BB * TT, 256>>>(x, ih4);
    k_rec<<<BB, 512>>>(hh4, out);
}